// round 15
// baseline (speedup 1.0000x reference)
#include <cuda_runtime.h>
#include <cuda_fp16.h>
#include <cuda_bf16.h>
#include <mma.h>

using namespace nvcuda;

// ---------------- problem-size constants (scratch sized to these) ----------
#define MAXN 100352            // >= 100000 nodes
#define MAXE 1703936           // >= 1600000 edges
#define MAXG 1024              // >= 1000 graphs
#define F1 64
#define F2 32
#define ELLW 64                // slots per node; P(in-deg >= 64) ~ 2e-18

// ---------------- static device scratch (no allocations allowed) ----------
static __device__ float  d_degw[MAXN];
static __device__ int    d_cnt[MAXN];
static __device__ int2   d_ell[(size_t)MAXN * ELLW];  // {src, edge_weight bits}
static __device__ __half d_W0h[128 * F1];    // W0 fp16 [128,64]
static __device__ __half d_W1h[F1 * F2];     // W1 fp16 [64,32]
static __device__ __half d_m0[MAXN * F1];    // dinv .* (x @ W0)      [N,64]
static __device__ __half d_m1[MAXN * F2];    // dinv .* (h0 @ W1)     [N,32]
static __device__ float  d_g [MAXG * F2];    // pooled                [G,32]

__device__ __forceinline__ float node_dinv(int i) {
    return rsqrtf(fmaxf(d_degw[i] + 1.0f, 1e-12f));
}

// ---------------- small utility kernels -----------------------------------
__global__ void k_zero(int n, int gsz) {
    int i = blockIdx.x * blockDim.x + threadIdx.x;
    if (i < n) { d_degw[i] = 0.f; d_cnt[i] = 0; }
    if (i < gsz) d_g[i] = 0.f;
}

__global__ void k_deg(const int* __restrict__ dst,
                      const float* __restrict__ w, int E) {
    int e = blockIdx.x * blockDim.x + threadIdx.x;
    if (e >= E) return;
    atomicAdd(&d_degw[dst[e]], w[e]);
}

// one-time weight conversion: W0 [128,64] and W1 [64,32] fp32 -> fp16
__global__ void __launch_bounds__(256) k_prep(const float* __restrict__ W0,
                                              const float* __restrict__ W1) {
    int t = threadIdx.x;
#pragma unroll
    for (int i = 0; i < 32; i++) {
        int idx = t + i * 256;            // 8192 W0 elems
        d_W0h[idx] = __float2half_rn(W0[idx]);
    }
#pragma unroll
    for (int i = 0; i < 8; i++) {
        int idx = t + i * 256;            // 2048 W1 elems
        d_W1h[idx] = __float2half_rn(W1[idx]);
    }
}

// ---------------- ELL fill: {src, raw weight} at atomic slot ---------------
__global__ void k_fill(const int* __restrict__ src, const int* __restrict__ dst,
                       const float* __restrict__ w, int E) {
    int e = blockIdx.x * blockDim.x + threadIdx.x;
    if (e >= E) return;
    int d = dst[e];
    int2 pk; pk.x = src[e]; pk.y = __float_as_int(w[e]);
    int slot = atomicAdd(&d_cnt[d], 1);
    if (slot < ELLW) d_ell[(size_t)d * ELLW + slot] = pk;
}

// ---------------- GEMM0: m0 = dinv .* (x @ W0)  (fp16 out) -----------------
__global__ void __launch_bounds__(256) k_gemm0(const float* __restrict__ x, int n) {
    __shared__ __align__(16) char sm[64 * 136 * 2 + 128 * 72 * 2];
    __shared__ float sdv[64];
    __half (*xs)[136] = reinterpret_cast<__half(*)[136]>(sm);
    __half (*ws)[72]  = reinterpret_cast<__half(*)[72]>(sm + 64 * 136 * 2);
    float  (*os)[68]  = reinterpret_cast<float(*)[68]>(sm);      // aliases xs

    int tid = threadIdx.x;
    int rowBase = blockIdx.x * 64;

    if (tid < 64) {
        int grow = rowBase + tid;
        sdv[tid] = (grow < n) ? node_dinv(grow) : 0.f;
    }
    // load x tile [64,128] fp32 -> fp16 smem
#pragma unroll
    for (int it = 0; it < 8; it++) {
        int idx = tid + it * 256;
        int r = idx >> 5, c = idx & 31;
        float4 v = make_float4(0.f, 0.f, 0.f, 0.f);
        int grow = rowBase + r;
        if (grow < n) v = *reinterpret_cast<const float4*>(x + (size_t)grow * 128 + c * 4);
        __half2 h0 = __floats2half2_rn(v.x, v.y);
        __half2 h1 = __floats2half2_rn(v.z, v.w);
        uint2 u; u.x = *reinterpret_cast<unsigned*>(&h0); u.y = *reinterpret_cast<unsigned*>(&h1);
        *reinterpret_cast<uint2*>(&xs[r][c * 4]) = u;
    }
    // load W0h [128,64] fp16 directly : 128 rows x 8 uint4 = 1024 jobs
#pragma unroll
    for (int it = 0; it < 4; it++) {
        int idx = tid + it * 256;
        int r = idx >> 3, c = idx & 7;
        uint4 v = *reinterpret_cast<const uint4*>(d_W0h + (size_t)r * 64 + c * 8);
        *reinterpret_cast<uint4*>(&ws[r][c * 8]) = v;
    }
    __syncthreads();

    int warp = tid >> 5;
    int rb = warp >> 1;          // 0..3 : row block (16 rows)
    int ch = warp & 1;           // 0..1 : column half (32 cols)

    wmma::fragment<wmma::accumulator, 16, 16, 16, float> c0, c1;
    wmma::fill_fragment(c0, 0.f);
    wmma::fill_fragment(c1, 0.f);
#pragma unroll
    for (int k = 0; k < 8; k++) {
        wmma::fragment<wmma::matrix_a, 16, 16, 16, __half, wmma::row_major> a;
        wmma::load_matrix_sync(a, &xs[rb * 16][k * 16], 136);
        wmma::fragment<wmma::matrix_b, 16, 16, 16, __half, wmma::row_major> b0, b1;
        wmma::load_matrix_sync(b0, &ws[k * 16][ch * 32], 72);
        wmma::load_matrix_sync(b1, &ws[k * 16][ch * 32 + 16], 72);
        wmma::mma_sync(c0, a, b0, c0);
        wmma::mma_sync(c1, a, b1, c1);
    }
    __syncthreads();             // xs no longer needed; reuse as float out
    wmma::store_matrix_sync(&os[rb * 16][ch * 32], c0, 68, wmma::mem_row_major);
    wmma::store_matrix_sync(&os[rb * 16][ch * 32 + 16], c1, 68, wmma::mem_row_major);
    __syncthreads();

#pragma unroll
    for (int it = 0; it < 8; it++) {
        int idx = tid + it * 256;
        int r = idx >> 5, c2 = idx & 31;
        int grow = rowBase + r;
        if (grow < n) {
            float dv = sdv[r];
            __half2 h = __floats2half2_rn(os[r][c2 * 2] * dv, os[r][c2 * 2 + 1] * dv);
            reinterpret_cast<__half2*>(d_m0 + (size_t)grow * 64)[c2] = h;
        }
    }
}

// ------- fused agg0 + GEMM1: m1 = dinv .* (relu(agg+b0) @ W1)  fp16 --------
// h[d] = relu(dinv[d]*(sum_e ew*m0[src] + m0[d]) + b0)   (m0 pre-scaled)
__global__ void __launch_bounds__(512) k_agg0_gemm1(const float* __restrict__ b0, int n) {
    __shared__ __align__(16) char sm[64 * 72 * 2 + 64 * 40 * 2];
    __shared__ float sdv[64];
    __half (*xs)[72] = reinterpret_cast<__half(*)[72]>(sm);
    __half (*ws)[40] = reinterpret_cast<__half(*)[40]>(sm + 64 * 72 * 2);
    float  (*os)[36] = reinterpret_cast<float(*)[36]>(sm);       // aliases xs

    int tid = threadIdx.x;
    int base = blockIdx.x * 64;
    int warp = tid >> 5;
    int lane = tid & 31;

    if (tid < 64) {
        int grow = base + tid;
        sdv[tid] = (grow < n) ? node_dinv(grow) : 0.f;
    }
    // load W1h [64,32] fp16 : 64 rows x 4 uint4 = 256 jobs
    if (tid < 256) {
        int r = tid >> 2, c = tid & 3;
        uint4 v = *reinterpret_cast<const uint4*>(d_W1h + (size_t)r * 32 + c * 8);
        *reinterpret_cast<uint4*>(&ws[r][c * 8]) = v;
    }
    __syncthreads();

    // aggregate 4 nodes per warp into xs rows (8-edge unrolled gather)
    const __half2* m = reinterpret_cast<const __half2*>(d_m0);
    float bx = b0[2 * lane], by = b0[2 * lane + 1];
#pragma unroll
    for (int i = 0; i < 4; i++) {
        int node = base + warp * 4 + i;
        int row = warp * 4 + i;
        if (node < n) {
            float2 mm = __half22float2(m[(size_t)node * 32 + lane]);
            float ax = mm.x, ay = mm.y;          // self term (pre-scaled m0)
            const int2* ell = d_ell + (size_t)node * ELLW;
            int cnt = d_cnt[node]; if (cnt > ELLW) cnt = ELLW;
            int e = 0;
            for (; e + 8 <= cnt; e += 8) {
                int2 p[8];
#pragma unroll
                for (int j = 0; j < 8; j++) p[j] = ell[e + j];
                float2 v[8];
#pragma unroll
                for (int j = 0; j < 8; j++) v[j] = __half22float2(m[(size_t)p[j].x * 32 + lane]);
#pragma unroll
                for (int j = 0; j < 8; j++) {
                    float w = __int_as_float(p[j].y);
                    ax += w * v[j].x; ay += w * v[j].y;
                }
            }
            for (; e < cnt; e++) {
                int2 p = ell[e];
                float2 v = __half22float2(m[(size_t)p.x * 32 + lane]);
                float w = __int_as_float(p.y);
                ax += w * v.x; ay += w * v.y;
            }
            float dv = sdv[row];
            ax = fmaxf(ax * dv + bx, 0.f); ay = fmaxf(ay * dv + by, 0.f);
            *reinterpret_cast<__half2*>(&xs[row][lane * 2]) = __floats2half2_rn(ax, ay);
        } else {
            *reinterpret_cast<__half2*>(&xs[row][lane * 2]) = __half2half2(__float2half(0.f));
        }
    }
    __syncthreads();

    // wmma: warps 0..7, each computes one 16x16 block of the 64x32 output
    if (warp < 8) {
        int rb = warp >> 1;      // 0..3
        int cb = warp & 1;       // 0..1
        wmma::fragment<wmma::accumulator, 16, 16, 16, float> c0;
        wmma::fill_fragment(c0, 0.f);
#pragma unroll
        for (int k = 0; k < 4; k++) {
            wmma::fragment<wmma::matrix_a, 16, 16, 16, __half, wmma::row_major> a;
            wmma::load_matrix_sync(a, &xs[rb * 16][k * 16], 72);
            wmma::fragment<wmma::matrix_b, 16, 16, 16, __half, wmma::row_major> b;
            wmma::load_matrix_sync(b, &ws[k * 16][cb * 16], 40);
            wmma::mma_sync(c0, a, b, c0);
        }
        __syncthreads();         // all mma reads of xs done
        wmma::store_matrix_sync(&os[rb * 16][cb * 16], c0, 36, wmma::mem_row_major);
    } else {
        __syncthreads();
    }
    __syncthreads();

    // write out m1 = dinv .* os, fp16 : 64 rows x 16 half2 = 1024 jobs
#pragma unroll
    for (int it = 0; it < 2; it++) {
        int idx = tid + it * 512;
        int r = idx >> 4, c2 = idx & 15;
        int grow = base + r;
        if (grow < n) {
            float dv = sdv[r];
            __half2 h = __floats2half2_rn(os[r][c2 * 2] * dv, os[r][c2 * 2 + 1] * dv);
            reinterpret_cast<__half2*>(d_m1 + (size_t)grow * 32)[c2] = h;
        }
    }
}

// ---------------- agg1 + pooling: g[graph] += relu(agg + b1) ---------------
__global__ void __launch_bounds__(256) k_agg1(const float* __restrict__ b1,
                                              const int* __restrict__ ngi, int n) {
    int warp = (blockIdx.x * blockDim.x + threadIdx.x) >> 5;
    int lane = threadIdx.x & 31;
    if (warp >= n) return;
    float acc = __half2float(d_m1[(size_t)warp * 32 + lane]);   // self (pre-scaled)
    const int2* ell = d_ell + (size_t)warp * ELLW;
    int cnt = d_cnt[warp]; if (cnt > ELLW) cnt = ELLW;
    int e = 0;
    for (; e + 8 <= cnt; e += 8) {
        int2 p[8];
#pragma unroll
        for (int j = 0; j < 8; j++) p[j] = ell[e + j];
        float v[8];
#pragma unroll
        for (int j = 0; j < 8; j++) v[j] = __half2float(d_m1[(size_t)p[j].x * 32 + lane]);
#pragma unroll
        for (int j = 0; j < 8; j++) acc += __int_as_float(p[j].y) * v[j];
    }
    for (; e < cnt; e++) {
        int2 p = ell[e];
        acc += __int_as_float(p.y) * __half2float(d_m1[(size_t)p.x * 32 + lane]);
    }
    float h = fmaxf(acc * node_dinv(warp) + b1[lane], 0.f);
    int g = ngi[warp];
    atomicAdd(&d_g[(size_t)g * 32 + lane], h);
}

// ---------------- MLP head: logits = relu(g@Wm1+bm1)@Wm2+bm2 ---------------
__global__ void __launch_bounds__(128) k_mlp(const float* __restrict__ Wm1,
                                             const float* __restrict__ bm1,
                                             const float* __restrict__ Wm2,
                                             const float* __restrict__ bm2,
                                             float* __restrict__ out, int G) {
    int gi = blockIdx.x;
    if (gi >= G) return;
    __shared__ float gs[32];
    __shared__ float red0[4], red1[4];
    int t = threadIdx.x;
    if (t < 32) gs[t] = d_g[(size_t)gi * 32 + t];
    __syncthreads();
    float acc = bm1[t];
#pragma unroll
    for (int k = 0; k < 32; k++) acc += gs[k] * Wm1[k * 128 + t];
    float h = fmaxf(acc, 0.f);
    float p0 = h * Wm2[t * 2 + 0];
    float p1 = h * Wm2[t * 2 + 1];
#pragma unroll
    for (int off = 16; off > 0; off >>= 1) {
        p0 += __shfl_down_sync(0xffffffffu, p0, off);
        p1 += __shfl_down_sync(0xffffffffu, p1, off);
    }
    if ((t & 31) == 0) { red0[t >> 5] = p0; red1[t >> 5] = p1; }
    __syncthreads();
    if (t == 0) {
        out[gi * 2 + 0] = red0[0] + red0[1] + red0[2] + red0[3] + bm2[0];
        out[gi * 2 + 1] = red1[0] + red1[1] + red1[2] + red1[3] + bm2[1];
    }
}

// ---------------------------------------------------------------------------
extern "C" void kernel_launch(void* const* d_in, const int* in_sizes, int n_in,
                              void* d_out, int out_size) {
    const float* x   = (const float*)d_in[0];
    const int*   ei  = (const int*)d_in[1];
    const float* ew  = (const float*)d_in[2];
    const int*   ngi = (const int*)d_in[3];
    const float* W0  = (const float*)d_in[4];
    const float* b0  = (const float*)d_in[5];
    const float* W1  = (const float*)d_in[6];
    const float* b1  = (const float*)d_in[7];
    const float* Wm1 = (const float*)d_in[8];
    const float* bm1 = (const float*)d_in[9];
    const float* Wm2 = (const float*)d_in[10];
    const float* bm2 = (const float*)d_in[11];
    float* out = (float*)d_out;

    int N = in_sizes[3];            // node_graph_index count
    int E = in_sizes[1] / 2;        // edge_index is [2, E]
    int G = out_size / 2;
    if (N > MAXN) N = MAXN;
    if (E > MAXE) E = MAXE;
    if (G > MAXG) G = MAXG;

    const int* e_src = ei;
    const int* e_dst = ei + E;

    // one-time side-stream + events (created outside any capture; reused in it)
    static cudaStream_t s_aux = nullptr;
    static cudaEvent_t  s_f0 = nullptr, s_f1 = nullptr, s_join = nullptr;
    if (s_aux == nullptr) {
        cudaStreamCreateWithFlags(&s_aux, cudaStreamNonBlocking);
        cudaEventCreateWithFlags(&s_f0, cudaEventDisableTiming);
        cudaEventCreateWithFlags(&s_f1, cudaEventDisableTiming);
        cudaEventCreateWithFlags(&s_join, cudaEventDisableTiming);
    }

    // fork aux early: weight conversion overlaps zero/deg
    cudaEventRecord(s_f0, 0);
    cudaStreamWaitEvent(s_aux, s_f0, 0);
    k_prep<<<1, 256, 0, s_aux>>>(W0, W1);

    // main: zero + degree accumulation
    k_zero<<<(N + 255) / 256, 256>>>(N, G * 32);
    k_deg<<<(E + 255) / 256, 256>>>(e_dst, ew, E);

    // aux: gemm0 needs degw (after deg) and W0h (after prep, same stream)
    cudaEventRecord(s_f1, 0);
    cudaStreamWaitEvent(s_aux, s_f1, 0);
    k_gemm0<<<(N + 63) / 64, 256, 0, s_aux>>>(x, N);
    cudaEventRecord(s_join, s_aux);

    // main: ELL fill overlaps gemm0
    k_fill<<<(E + 255) / 256, 256>>>(e_src, e_dst, ew, E);

    // join, then fused layer-1-agg + layer-2-GEMM, agg1+pool, MLP head
    cudaStreamWaitEvent(0, s_join, 0);
    k_agg0_gemm1<<<(N + 63) / 64, 512>>>(b0, N);                    // 5 <- ncu -s 5
    k_agg1<<<(N + 7) / 8, 256>>>(b1, ngi, N);
    k_mlp<<<G, 128>>>(Wm1, bm1, Wm2, bm2, out, G);
}